// round 17
// baseline (speedup 1.0000x reference)
#include <cuda_runtime.h>
#include <cuda_fp16.h>
#include <math.h>
#include <stdint.h>

// ----------------------------------------------------------------------------
// Problem constants
// ----------------------------------------------------------------------------
#define B_   2
#define T_   2048
#define S_   2048
#define ED_  1024
#define NH_  16
#define HD_  64
#define FF_  4096
#define BT_  (B_ * T_)          // 4096 rows

// ----------------------------------------------------------------------------
// Device scratch (no allocations allowed -> __device__ globals)
// ----------------------------------------------------------------------------
__device__ __half g_Hh  [BT_ * ED_];     // LN output (fp16)
__device__ __half g_Qh  [BT_ * ED_];
__device__ __half g_Kh  [BT_ * ED_];
__device__ __half g_Vh  [BT_ * ED_];
__device__ __half g_Ah  [BT_ * ED_];     // attention output (fp16)
__device__ __half g_F1h [BT_ * FF_];     // FFN hidden (fp16)
__device__ __half g_encH[BT_ * ED_];     // encoder outputs (fp16)
__device__ __half g_W16 [ED_ * FF_];     // converted weight scratch
__device__ float  g_X1  [BT_ * ED_];     // residual after self-attn (fp32)

// ----------------------------------------------------------------------------
// Helpers
// ----------------------------------------------------------------------------
__device__ __forceinline__ uint32_t smem_u32(const void* p) {
    uint32_t a;
    asm("{ .reg .u64 t; cvta.to.shared.u64 t, %1; cvt.u32.u64 %0, t; }"
        : "=r"(a) : "l"(p));
    return a;
}

__device__ __forceinline__ uint32_t pack2h(float lo, float hi) {
    __half2 h = __floats2half2_rn(lo, hi);
    return *reinterpret_cast<uint32_t*>(&h);
}

__device__ __forceinline__ float ex2(float x) {
    float y;
    asm("ex2.approx.ftz.f32 %0, %1;" : "=f"(y) : "f"(x));
    return y;
}

#define CP_ASYNC16(dst, src) \
    asm volatile("cp.async.cg.shared.global [%0], [%1], 16;" \
                 :: "r"(dst), "l"(src) : "memory")
#define CP_COMMIT() asm volatile("cp.async.commit_group;" ::: "memory")
#define CP_WAIT0()  asm volatile("cp.async.wait_group 0;" ::: "memory")

#define LDSM4(r, a) \
    asm volatile("ldmatrix.sync.aligned.m8n8.x4.shared.b16 {%0,%1,%2,%3}, [%4];" \
        : "=r"((r)[0]), "=r"((r)[1]), "=r"((r)[2]), "=r"((r)[3]) : "r"(a))
#define LDSM4T(r, a) \
    asm volatile("ldmatrix.sync.aligned.m8n8.x4.trans.shared.b16 {%0,%1,%2,%3}, [%4];" \
        : "=r"((r)[0]), "=r"((r)[1]), "=r"((r)[2]), "=r"((r)[3]) : "r"(a))

#define HMMA(c, a, b0, b1) \
    asm volatile("mma.sync.aligned.m16n8k16.row.col.f32.f16.f16.f32 " \
        "{%0,%1,%2,%3},{%4,%5,%6,%7},{%8,%9},{%0,%1,%2,%3};" \
        : "+f"((c)[0]), "+f"((c)[1]), "+f"((c)[2]), "+f"((c)[3]) \
        : "r"((a)[0]), "r"((a)[1]), "r"((a)[2]), "r"((a)[3]), "r"(b0), "r"(b1))

// ----------------------------------------------------------------------------
// fp32 -> fp16 conversion (weights / encoder), 8 elems per thread
// ----------------------------------------------------------------------------
__global__ __launch_bounds__(256) void f2h_k(const float* __restrict__ in,
                                             __half* __restrict__ out) {
    long i = ((long)blockIdx.x * 256 + threadIdx.x) * 8;
    float4 a = *(const float4*)(in + i);
    float4 b = *(const float4*)(in + i + 4);
    uint4 u;
    u.x = pack2h(a.x, a.y); u.y = pack2h(a.z, a.w);
    u.z = pack2h(b.x, b.y); u.w = pack2h(b.z, b.w);
    *(uint4*)(out + i) = u;
}

// ----------------------------------------------------------------------------
// LayerNorm: one block per row of 1024, fp32 in -> fp16 out
// ----------------------------------------------------------------------------
__global__ __launch_bounds__(256) void ln_k(const float* __restrict__ x,
                                            const float* __restrict__ g,
                                            const float* __restrict__ b,
                                            __half* __restrict__ o) {
    __shared__ float red[8];
    __shared__ float s_mu, s_rstd;
    long base = (long)blockIdx.x * ED_;
    int t = threadIdx.x;
    float4 v = *(const float4*)(x + base + t * 4);

    float s = v.x + v.y + v.z + v.w;
    #pragma unroll
    for (int off = 16; off; off >>= 1) s += __shfl_xor_sync(0xffffffffu, s, off);
    if ((t & 31) == 0) red[t >> 5] = s;
    __syncthreads();
    if (t == 0) {
        float tot = 0.f;
        #pragma unroll
        for (int i = 0; i < 8; i++) tot += red[i];
        s_mu = tot * (1.0f / ED_);
    }
    __syncthreads();
    float mu = s_mu;
    float dx = v.x - mu, dy = v.y - mu, dz = v.z - mu, dw = v.w - mu;
    float ss = dx * dx + dy * dy + dz * dz + dw * dw;
    #pragma unroll
    for (int off = 16; off; off >>= 1) ss += __shfl_xor_sync(0xffffffffu, ss, off);
    __syncthreads();
    if ((t & 31) == 0) red[t >> 5] = ss;
    __syncthreads();
    if (t == 0) {
        float tot = 0.f;
        #pragma unroll
        for (int i = 0; i < 8; i++) tot += red[i];
        s_rstd = rsqrtf(tot * (1.0f / ED_) + 1e-5f);
    }
    __syncthreads();
    float rstd = s_rstd;
    float4 gv = *(const float4*)(g + t * 4);
    float4 bv = *(const float4*)(b + t * 4);
    float ox = dx * rstd * gv.x + bv.x;
    float oy = dy * rstd * gv.y + bv.y;
    float oz = dz * rstd * gv.z + bv.z;
    float ow = dw * rstd * gv.w + bv.w;
    uint2 u;
    u.x = pack2h(ox, oy); u.y = pack2h(oz, ow);
    *(uint2*)(o + base + t * 4) = u;
}

// ----------------------------------------------------------------------------
// fp16 tensor-core GEMM: C[M,N] = (A[M,K] @ Bw[K,N] + bias) * alpha
//                         (relu) (+R fp32) -> fp32 or fp16 out
// BM=256, BN=128, BK=32, 512 threads (16 warps 4x4), warp tile 64x32.
// Projections/FF2: grid = exactly 128 blocks = single wave on 148 SMs.
// Single __syncthreads per k-iter: wait -> sync -> issue next loads -> compute.
// ----------------------------------------------------------------------------
#define HG_SMEM (2*256*40*2 + 2*32*136*2)   // 58368 B

template <bool RELU, bool RES, bool OUTH>
__global__ __launch_bounds__(512) void hgemm(
    const __half* __restrict__ A,    // [M, K]
    const __half* __restrict__ Bw,   // [K, N]
    const float* __restrict__ bias,  // [N]
    const float* __restrict__ R,     // [M, N] fp32 residual
    float* __restrict__ Cf,          // fp32 out (if !OUTH)
    __half* __restrict__ Ch,         // fp16 out (if OUTH)
    int K, int N, float alpha) {

    extern __shared__ __half dsm[];
    __half (*As)[256][40] = (__half(*)[256][40])dsm;
    __half (*Bs)[32][136] = (__half(*)[32][136])(dsm + 2 * 256 * 40);

    int t = threadIdx.x, lane = t & 31, w = t >> 5;
    int wm = w >> 2, wn = w & 3;                 // 4x4 warp grid
    int bm = blockIdx.y * 256, bn = blockIdx.x * 128;

    auto load_tile = [&](int buf, int kt) {
        #pragma unroll
        for (int i = 0; i < 2; i++) {
            int c = t + i * 512;
            int row = c >> 2, ch = c & 3;
            CP_ASYNC16(smem_u32(&As[buf][row][ch * 8]),
                       A + (long)(bm + row) * K + kt + ch * 8);
        }
        {
            int row = t >> 4, ch = t & 15;
            CP_ASYNC16(smem_u32(&Bs[buf][row][ch * 8]),
                       Bw + (long)(kt + row) * N + bn + ch * 8);
        }
        CP_COMMIT();
    };

    float acc[4][4][4];
    #pragma unroll
    for (int mi = 0; mi < 4; mi++)
        #pragma unroll
        for (int ni = 0; ni < 4; ni++)
            #pragma unroll
            for (int c = 0; c < 4; c++) acc[mi][ni][c] = 0.f;

    int nt = K / 32;
    load_tile(0, 0);

    for (int i = 0; i < nt; i++) {
        CP_WAIT0();
        __syncthreads();
        if (i + 1 < nt) load_tile((i + 1) & 1, (i + 1) * 32);
        int buf = i & 1;
        #pragma unroll
        for (int ks = 0; ks < 2; ks++) {
            uint32_t a[4][4];
            #pragma unroll
            for (int mi = 0; mi < 4; mi++)
                LDSM4(a[mi], smem_u32(&As[buf][wm * 64 + mi * 16 + (lane & 15)]
                                          [ks * 16 + (lane >> 4) * 8]));
            #pragma unroll
            for (int nj = 0; nj < 2; nj++) {
                uint32_t bt[4];
                LDSM4T(bt, smem_u32(&Bs[buf][ks * 16 + (lane & 15)]
                                        [wn * 32 + nj * 16 + (lane >> 4) * 8]));
                #pragma unroll
                for (int mi = 0; mi < 4; mi++) {
                    HMMA(acc[mi][nj * 2 + 0], a[mi], bt[0], bt[1]);
                    HMMA(acc[mi][nj * 2 + 1], a[mi], bt[2], bt[3]);
                }
            }
        }
    }

    // ---- epilogue ----
    #pragma unroll
    for (int mi = 0; mi < 4; mi++) {
        #pragma unroll
        for (int ni = 0; ni < 4; ni++) {
            int col = bn + wn * 32 + ni * 8 + (lane & 3) * 2;
            float b0 = bias[col], b1 = bias[col + 1];
            #pragma unroll
            for (int hh = 0; hh < 2; hh++) {
                int row = bm + wm * 64 + mi * 16 + (lane >> 2) + hh * 8;
                float v0 = (acc[mi][ni][hh * 2 + 0] + b0) * alpha;
                float v1 = (acc[mi][ni][hh * 2 + 1] + b1) * alpha;
                if (RELU) { v0 = fmaxf(v0, 0.f); v1 = fmaxf(v1, 0.f); }
                if (RES) {
                    float2 r2 = *(const float2*)&R[(long)row * N + col];
                    v0 += r2.x; v1 += r2.y;
                }
                if (OUTH) {
                    *(uint32_t*)&Ch[(long)row * N + col] = pack2h(v0, v1);
                } else {
                    float2 o; o.x = v0; o.y = v1;
                    *(float2*)&Cf[(long)row * N + col] = o;
                }
            }
        }
    }
}

// ----------------------------------------------------------------------------
// Fused flash attention, fp16 mma, double-buffered K/V tiles.
// One block per (q-tile 128, head, batch); 256 threads = 8 warps;
// warp w owns q rows [w*16, w*16+16).
// Q pre-scaled by log2(e)/sqrt(64) in projection epilogue -> ex2 softmax.
// P fragments built directly from S accumulator registers (no smem round-trip).
// ----------------------------------------------------------------------------
#define FTILE (128 * 72)                     // halves per K or V tile
#define FSMEM2 (4 * FTILE * 2)               // 73728 B

template <bool CAUSAL>
__global__ __launch_bounds__(256) void hflash(
    const __half* __restrict__ Qg, const __half* __restrict__ Kg,
    const __half* __restrict__ Vg, __half* __restrict__ Og) {

    extern __shared__ __half fsm[];
    // buf p: K tile at fsm + (2p)*FTILE, V tile at fsm + (2p+1)*FTILE, stride 72

    int t = threadIdx.x, lane = t & 31, w = t >> 5;
    int j = lane & 3, r4 = lane >> 2;
    int qt = CAUSAL ? (gridDim.x - 1 - blockIdx.x) : blockIdx.x;
    int h = blockIdx.y, b = blockIdx.z;
    int hoff = h * HD_;
    long qrow0 = (long)b * T_ + qt * 128;
    long krow0 = (long)b * S_;

    auto load_kv = [&](int p, int kt) {
        __half* Kp = fsm + (2 * p) * FTILE;
        __half* Vp = fsm + (2 * p + 1) * FTILE;
        long kb = krow0 + (long)kt * 128;
        #pragma unroll
        for (int i = 0; i < 4; i++) {
            int c = t + i * 256; int row = c >> 3, ch = c & 7;
            long go = (kb + row) * ED_ + hoff + ch * 8;
            CP_ASYNC16(smem_u32(&Kp[row * 72 + ch * 8]), Kg + go);
            CP_ASYNC16(smem_u32(&Vp[row * 72 + ch * 8]), Vg + go);
        }
        CP_COMMIT();
    };

    // ---- stage Q (into buf0 K region), extract A-fragments ----
    {
        __half* K0 = fsm;
        #pragma unroll
        for (int i = 0; i < 4; i++) {
            int c = t + i * 256; int row = c >> 3, ch = c & 7;
            CP_ASYNC16(smem_u32(&K0[row * 72 + ch * 8]),
                       Qg + (qrow0 + row) * ED_ + hoff + ch * 8);
        }
        CP_COMMIT(); CP_WAIT0();
    }
    __syncthreads();
    uint32_t aq[4][4];
    #pragma unroll
    for (int ks = 0; ks < 4; ks++)
        LDSM4(aq[ks], smem_u32(&fsm[(w * 16 + (lane & 15)) * 72
                                    + ks * 16 + (lane >> 4) * 8]));
    __syncthreads();

    load_kv(0, 0);

    float m[2] = {-1e30f, -1e30f};
    float l[2] = {0.f, 0.f};
    float accO[8][4];
    #pragma unroll
    for (int nv = 0; nv < 8; nv++)
        #pragma unroll
        for (int c = 0; c < 4; c++) accO[nv][c] = 0.f;

    int ktiles = CAUSAL ? (qt + 1) : (S_ / 128);

    for (int kt = 0; kt < ktiles; kt++) {
        CP_WAIT0();
        __syncthreads();
        if (kt + 1 < ktiles) load_kv((kt + 1) & 1, kt + 1);
        int p = kt & 1;
        __half* Kp = fsm + (2 * p) * FTILE;
        __half* Vp = fsm + (2 * p + 1) * FTILE;

        // ---- S = Q @ K^T ----
        float accS[16][4];
        #pragma unroll
        for (int ni = 0; ni < 16; ni++)
            #pragma unroll
            for (int c = 0; c < 4; c++) accS[ni][c] = 0.f;

        #pragma unroll
        for (int ks = 0; ks < 4; ks++) {
            #pragma unroll
            for (int g = 0; g < 8; g++) {
                uint32_t bk[4];
                LDSM4(bk, smem_u32(&Kp[(g * 16 + (lane & 7) + ((lane >> 4) & 1) * 8) * 72
                                       + ks * 16 + ((lane >> 3) & 1) * 8]));
                HMMA(accS[g * 2 + 0], aq[ks], bk[0], bk[1]);
                HMMA(accS[g * 2 + 1], aq[ks], bk[2], bk[3]);
            }
        }

        // ---- causal mask on diagonal tile ----
        if (CAUSAL && kt == qt) {
            int rl0 = w * 16 + r4;
            #pragma unroll
            for (int ni = 0; ni < 16; ni++) {
                int n0 = ni * 8 + 2 * j;
                if (n0 + 0 > rl0)     accS[ni][0] = -1e30f;
                if (n0 + 1 > rl0)     accS[ni][1] = -1e30f;
                if (n0 + 0 > rl0 + 8) accS[ni][2] = -1e30f;
                if (n0 + 1 > rl0 + 8) accS[ni][3] = -1e30f;
            }
        }

        // ---- online softmax (base-2; log2e folded into Q scale) ----
        #pragma unroll
        for (int hh = 0; hh < 2; hh++) {
            float mx = -1e30f;
            #pragma unroll
            for (int ni = 0; ni < 16; ni++)
                mx = fmaxf(mx, fmaxf(accS[ni][2 * hh], accS[ni][2 * hh + 1]));
            mx = fmaxf(mx, __shfl_xor_sync(0xffffffffu, mx, 1));
            mx = fmaxf(mx, __shfl_xor_sync(0xffffffffu, mx, 2));
            float mnew = fmaxf(m[hh], mx);
            float fac = ex2(m[hh] - mnew);
            float sum = 0.f;
            #pragma unroll
            for (int ni = 0; ni < 16; ni++) {
                float p0 = ex2(accS[ni][2 * hh] - mnew);
                float p1 = ex2(accS[ni][2 * hh + 1] - mnew);
                accS[ni][2 * hh] = p0; accS[ni][2 * hh + 1] = p1;
                sum += p0 + p1;
            }
            sum += __shfl_xor_sync(0xffffffffu, sum, 1);
            sum += __shfl_xor_sync(0xffffffffu, sum, 2);
            l[hh] = l[hh] * fac + sum;
            m[hh] = mnew;
            #pragma unroll
            for (int nv = 0; nv < 8; nv++) {
                accO[nv][2 * hh]     *= fac;
                accO[nv][2 * hh + 1] *= fac;
            }
        }

        // ---- O += P @ V ; P A-frags built straight from accS registers ----
        #pragma unroll
        for (int kp = 0; kp < 8; kp++) {
            uint32_t pa[4];
            pa[0] = pack2h(accS[2 * kp][0],     accS[2 * kp][1]);
            pa[1] = pack2h(accS[2 * kp][2],     accS[2 * kp][3]);
            pa[2] = pack2h(accS[2 * kp + 1][0], accS[2 * kp + 1][1]);
            pa[3] = pack2h(accS[2 * kp + 1][2], accS[2 * kp + 1][3]);
            #pragma unroll
            for (int dj = 0; dj < 4; dj++) {
                uint32_t bv[4];
                LDSM4T(bv, smem_u32(&Vp[(kp * 16 + (lane & 15)) * 72
                                        + dj * 16 + (lane >> 4) * 8]));
                HMMA(accO[dj * 2 + 0], pa, bv[0], bv[1]);
                HMMA(accO[dj * 2 + 1], pa, bv[2], bv[3]);
            }
        }
    }

    // ---- epilogue: normalize, write O (fp16) ----
    float inv0 = 1.0f / l[0], inv1 = 1.0f / l[1];
    #pragma unroll
    for (int nv = 0; nv < 8; nv++) {
        int col = hoff + nv * 8 + 2 * j;
        long row = qrow0 + w * 16 + r4;
        *(uint32_t*)&Og[row * ED_ + col]       = pack2h(accO[nv][0] * inv0, accO[nv][1] * inv0);
        *(uint32_t*)&Og[(row + 8) * ED_ + col] = pack2h(accO[nv][2] * inv1, accO[nv][3] * inv1);
    }
}

// ----------------------------------------------------------------------------
// Host orchestration
// ----------------------------------------------------------------------------
extern "C" void kernel_launch(void* const* d_in, const int* in_sizes, int n_in,
                              void* d_out, int out_size) {
    const float* x     = (const float*)d_in[0];
    const float* enc   = (const float*)d_in[1];
    // d_in[2] = tgt_mask (always causal tril; handled analytically)
    const float* sa_wq = (const float*)d_in[3];
    const float* sa_bq = (const float*)d_in[4];
    const float* sa_wk = (const float*)d_in[5];
    const float* sa_bk = (const float*)d_in[6];
    const float* sa_wv = (const float*)d_in[7];
    const float* sa_bv = (const float*)d_in[8];
    const float* sa_wo = (const float*)d_in[9];
    const float* sa_bo = (const float*)d_in[10];
    const float* ca_wq = (const float*)d_in[11];
    const float* ca_bq = (const float*)d_in[12];
    const float* ca_wk = (const float*)d_in[13];
    const float* ca_bk = (const float*)d_in[14];
    const float* ca_wv = (const float*)d_in[15];
    const float* ca_bv = (const float*)d_in[16];
    const float* ca_wo = (const float*)d_in[17];
    const float* ca_bo = (const float*)d_in[18];
    const float* ff_w1 = (const float*)d_in[19];
    const float* ff_b1 = (const float*)d_in[20];
    const float* ff_w2 = (const float*)d_in[21];
    const float* ff_b2 = (const float*)d_in[22];
    const float* ln1g  = (const float*)d_in[23];
    const float* ln1b  = (const float*)d_in[24];
    const float* ln2g  = (const float*)d_in[25];
    const float* ln2b  = (const float*)d_in[26];
    const float* ln3g  = (const float*)d_in[27];
    const float* ln3b  = (const float*)d_in[28];
    float* out = (float*)d_out;

    __half *Hh, *Qh, *Kh, *Vh, *Ah, *F1h, *encH, *W16;
    float  *X1;
    cudaGetSymbolAddress((void**)&Hh,   g_Hh);
    cudaGetSymbolAddress((void**)&Qh,   g_Qh);
    cudaGetSymbolAddress((void**)&Kh,   g_Kh);
    cudaGetSymbolAddress((void**)&Vh,   g_Vh);
    cudaGetSymbolAddress((void**)&Ah,   g_Ah);
    cudaGetSymbolAddress((void**)&F1h,  g_F1h);
    cudaGetSymbolAddress((void**)&encH, g_encH);
    cudaGetSymbolAddress((void**)&W16,  g_W16);
    cudaGetSymbolAddress((void**)&X1,   g_X1);

    static bool attr_done = false;
    if (!attr_done) {
        cudaFuncSetAttribute(hflash<true>,
            cudaFuncAttributeMaxDynamicSharedMemorySize, FSMEM2);
        cudaFuncSetAttribute(hflash<false>,
            cudaFuncAttributeMaxDynamicSharedMemorySize, FSMEM2);
        cudaFuncSetAttribute(hgemm<false, false, true>,
            cudaFuncAttributeMaxDynamicSharedMemorySize, HG_SMEM);
        cudaFuncSetAttribute(hgemm<false, true, false>,
            cudaFuncAttributeMaxDynamicSharedMemorySize, HG_SMEM);
        cudaFuncSetAttribute(hgemm<true, false, true>,
            cudaFuncAttributeMaxDynamicSharedMemorySize, HG_SMEM);
        attr_done = true;
    }

    // 1/sqrt(64) * log2(e) folded into Q projection (softmax runs in base 2)
    const float qscale = 0.125f * 1.4426950408889634f;
    const int gW1M = (ED_ * ED_) / 2048;    // 512 blocks (1M elems)
    const int gW4M = (ED_ * FF_) / 2048;    // 2048 blocks (4M elems)

    dim3 gP(ED_ / 128, BT_ / 256);          // (8, 16) = 128 blocks: one wave
    dim3 gF1(FF_ / 128, BT_ / 256);         // (32, 16)
    dim3 gFlash(T_ / 128, NH_, B_);         // (16, 16, 2)

    // encoder outputs -> fp16 (used by both CA K and V projections)
    f2h_k<<<gW4M, 256>>>(enc, encH);

    // ---------------- self-attention block ----------------
    ln_k<<<BT_, 256>>>(x, ln1g, ln1b, Hh);
    f2h_k<<<gW1M, 256>>>(sa_wq, W16);
    hgemm<false, false, true><<<gP, 512, HG_SMEM>>>(Hh, W16, sa_bq, nullptr, nullptr, Qh, ED_, ED_, qscale);
    f2h_k<<<gW1M, 256>>>(sa_wk, W16);
    hgemm<false, false, true><<<gP, 512, HG_SMEM>>>(Hh, W16, sa_bk, nullptr, nullptr, Kh, ED_, ED_, 1.0f);
    f2h_k<<<gW1M, 256>>>(sa_wv, W16);
    hgemm<false, false, true><<<gP, 512, HG_SMEM>>>(Hh, W16, sa_bv, nullptr, nullptr, Vh, ED_, ED_, 1.0f);
    hflash<true><<<gFlash, 256, FSMEM2>>>(Qh, Kh, Vh, Ah);
    f2h_k<<<gW1M, 256>>>(sa_wo, W16);
    hgemm<false, true, false><<<gP, 512, HG_SMEM>>>(Ah, W16, sa_bo, x, X1, nullptr, ED_, ED_, 1.0f);

    // ---------------- cross-attention block ----------------
    ln_k<<<BT_, 256>>>(X1, ln2g, ln2b, Hh);
    f2h_k<<<gW1M, 256>>>(ca_wq, W16);
    hgemm<false, false, true><<<gP, 512, HG_SMEM>>>(Hh, W16, ca_bq, nullptr, nullptr, Qh, ED_, ED_, qscale);
    f2h_k<<<gW1M, 256>>>(ca_wk, W16);
    hgemm<false, false, true><<<gP, 512, HG_SMEM>>>(encH, W16, ca_bk, nullptr, nullptr, Kh, ED_, ED_, 1.0f);
    f2h_k<<<gW1M, 256>>>(ca_wv, W16);
    hgemm<false, false, true><<<gP, 512, HG_SMEM>>>(encH, W16, ca_bv, nullptr, nullptr, Vh, ED_, ED_, 1.0f);
    hflash<false><<<gFlash, 256, FSMEM2>>>(Qh, Kh, Vh, Ah);
    f2h_k<<<gW1M, 256>>>(ca_wo, W16);
    hgemm<false, true, false><<<gP, 512, HG_SMEM>>>(Ah, W16, ca_bo, X1, out, nullptr, ED_, ED_, 1.0f);

    // ---------------- feed-forward block ----------------
    ln_k<<<BT_, 256>>>(out, ln3g, ln3b, Hh);
    f2h_k<<<gW4M, 256>>>(ff_w1, W16);
    hgemm<true, false, true><<<gF1, 512, HG_SMEM>>>(Hh, W16, ff_b1, nullptr, nullptr, F1h, ED_, FF_, 1.0f);
    f2h_k<<<gW4M, 256>>>(ff_w2, W16);
    hgemm<false, true, false><<<gP, 512, HG_SMEM>>>(F1h, W16, ff_b2, out, out, nullptr, FF_, ED_, 1.0f);
}